// round 7
// baseline (speedup 1.0000x reference)
#include <cuda_runtime.h>
#include <cstdint>

// NTN: out[n,k] = relu( cos(x1@W1[k], x2@W2[k]) + [x1,x2]@V[k] + b[k] )
// R7: int8 split-2 IMMA m16n8k32 (hh + cross, ll dropped). Scales cancel in
// cosine. Fragment-major A and B in global scratch; no smem staging in main.

#define NN 32768
#define DD 128
#define KK 32
#define EPSN 1e-8f

// ---------------- global scratch ----------------
// A fragments: [mat][plane][rowtile16][ktile32][lane] (16B/lane)
__device__ uint4 gXq[2][2][2048][4][32];          // 16.8 MB
// B fragments: [k][mat][plane][ktile32][ntile8][lane] (8B/lane)
__device__ uint2 gWq[32][2][2][4][16][32];        // 4 MB
__device__ float gP2[(size_t)NN * KK];            // part2 + bias

// ---------------- helpers ----------------
static __device__ __forceinline__ uint32_t packs8(int a, int b, int c, int d) {
    return (uint32_t)(a & 0xff) | ((uint32_t)(b & 0xff) << 8)
         | ((uint32_t)(c & 0xff) << 16) | ((uint32_t)(d & 0xff) << 24);
}
// quantize 4 floats: q = rint(x*inv) (|q| <= 16256), h = rint(q/128), l = q-128h
static __device__ __forceinline__ void quant4(float4 f, float inv,
                                              uint32_t& hb, uint32_t& lb) {
    float q0 = rintf(f.x * inv), q1 = rintf(f.y * inv);
    float q2 = rintf(f.z * inv), q3 = rintf(f.w * inv);
    float h0 = rintf(q0 * 0.0078125f), h1 = rintf(q1 * 0.0078125f);
    float h2 = rintf(q2 * 0.0078125f), h3 = rintf(q3 * 0.0078125f);
    int l0 = (int)(q0 - 128.f * h0), l1 = (int)(q1 - 128.f * h1);
    int l2 = (int)(q2 - 128.f * h2), l3 = (int)(q3 - 128.f * h3);
    hb = packs8((int)h0, (int)h1, (int)h2, (int)h3);
    lb = packs8(l0, l1, l2, l3);
}

#define IMMA(C, A, B)                                                          \
    asm volatile("mma.sync.aligned.m16n8k32.row.col.s32.s8.s8.s32 "            \
                 "{%0,%1,%2,%3},{%4,%5,%6,%7},{%8,%9},{%0,%1,%2,%3};"          \
                 : "+r"((C)[0]), "+r"((C)[1]), "+r"((C)[2]), "+r"((C)[3])      \
                 : "r"((A).x), "r"((A).y), "r"((A).z), "r"((A).w),             \
                   "r"((B).x), "r"((B).y))

// ---------------- prep: X -> int8 hi/lo A-fragments ----------------
__global__ __launch_bounds__(256) void prep_x(const float* __restrict__ x1,
                                              const float* __restrict__ x2) {
    int wid  = (blockIdx.x * 256 + threadIdx.x) >> 5;   // 0..4095
    int lane = threadIdx.x & 31;
    int m  = wid >> 11;
    int rt = wid & 2047;
    const float* x = m ? x2 : x1;
    // per-row maxes for the 16 rows of this tile
    float scales[16];
    #pragma unroll
    for (int rr = 0; rr < 16; rr++) {
        float4 v = ((const float4*)(x + (size_t)(rt * 16 + rr) * DD))[lane];
        float mx = fmaxf(fmaxf(fabsf(v.x), fabsf(v.y)),
                         fmaxf(fabsf(v.z), fabsf(v.w)));
        #pragma unroll
        for (int o = 16; o; o >>= 1)
            mx = fmaxf(mx, __shfl_xor_sync(0xffffffffu, mx, o));
        scales[rr] = mx;
    }
    const int rr0 = lane >> 2, rr1 = rr0 + 8;
    float inv0 = scales[rr0] > 0.f ? 16256.f / scales[rr0] : 0.f;
    float inv1 = scales[rr1] > 0.f ? 16256.f / scales[rr1] : 0.f;
    const float* p0 = x + (size_t)(rt * 16 + rr0) * DD;
    const float* p1 = x + (size_t)(rt * 16 + rr1) * DD;
    #pragma unroll
    for (int kt = 0; kt < 4; kt++) {
        int c = kt * 32 + (lane & 3) * 4;
        uint32_t h0, h1, h2, h3, l0, l1, l2, l3;
        quant4(*(const float4*)(p0 + c),      inv0, h0, l0);  // a0: (r,   c)
        quant4(*(const float4*)(p1 + c),      inv1, h1, l1);  // a1: (r+8, c)
        quant4(*(const float4*)(p0 + c + 16), inv0, h2, l2);  // a2: (r,   c+16)
        quant4(*(const float4*)(p1 + c + 16), inv1, h3, l3);  // a3: (r+8, c+16)
        gXq[m][0][rt][kt][lane] = make_uint4(h0, h1, h2, h3);
        gXq[m][1][rt][kt][lane] = make_uint4(l0, l1, l2, l3);
    }
}

// ---------------- prep: W -> int8 hi/lo B-fragments (one block per k,mat) ----
__global__ __launch_bounds__(256) void prep_w(const float* __restrict__ W1,
                                              const float* __restrict__ W2) {
    __shared__ float red[256];
    const int m = blockIdx.x & 1, k = blockIdx.x >> 1;
    const float* w = (m ? W2 : W1) + (size_t)k * DD * DD;
    const int tid = threadIdx.x;
    float mx = 0.f;
    for (int i = tid; i < 4096; i += 256) {
        float4 v = ((const float4*)w)[i];
        mx = fmaxf(mx, fmaxf(fmaxf(fabsf(v.x), fabsf(v.y)),
                             fmaxf(fabsf(v.z), fabsf(v.w))));
    }
    red[tid] = mx;
    __syncthreads();
    for (int s = 128; s; s >>= 1) {
        if (tid < s) red[tid] = fmaxf(red[tid], red[tid + s]);
        __syncthreads();
    }
    const float inv = red[0] > 0.f ? 16256.f / red[0] : 0.f;
    #pragma unroll
    for (int i = 0; i < 8; i++) {
        int u    = tid + 256 * i;           // 0..2047
        int lane = u & 31;
        int nt   = (u >> 5) & 15;
        int kt   = u >> 9;
        int e    = nt * 8 + (lane >> 2);
        int d0   = kt * 32 + (lane & 3) * 4;
        uint32_t hb[2], lb[2];
        #pragma unroll
        for (int half = 0; half < 2; half++) {
            int hq[4], lq[4];
            #pragma unroll
            for (int j = 0; j < 4; j++) {
                float q  = rintf(w[(size_t)(d0 + half * 16 + j) * DD + e] * inv);
                float hf = rintf(q * 0.0078125f);
                hq[j] = (int)hf;
                lq[j] = (int)(q - 128.f * hf);
            }
            hb[half] = packs8(hq[0], hq[1], hq[2], hq[3]);
            lb[half] = packs8(lq[0], lq[1], lq[2], lq[3]);
        }
        gWq[k][m][0][kt][nt][lane] = make_uint2(hb[0], hb[1]);
        gWq[k][m][1][kt][nt][lane] = make_uint2(lb[0], lb[1]);
    }
}

// ---------------- prep: part2 + bias (exact fp32) ----------------
__global__ __launch_bounds__(256) void prep_p2(const float* __restrict__ x1,
                                               const float* __restrict__ x2,
                                               const float* __restrict__ Vg,
                                               const float* __restrict__ bg) {
    __shared__ float Vs[KK * 256];
    __shared__ float bs[KK];
    int tid = threadIdx.x;
    for (int i = tid; i < KK * 256; i += 256) Vs[i] = Vg[i];
    if (tid < KK) bs[tid] = bg[tid];
    __syncthreads();
    int n = blockIdx.x * 256 + tid;
    float acc[KK];
    #pragma unroll
    for (int k = 0; k < KK; k++) acc[k] = bs[k];
    const float4* xa = (const float4*)(x1 + (size_t)n * DD);
    const float4* xb = (const float4*)(x2 + (size_t)n * DD);
    #pragma unroll 4
    for (int f = 0; f < 32; f++) {
        float4 xv = xa[f];
        #pragma unroll
        for (int k = 0; k < KK; k++) {
            float4 vv = *(const float4*)(&Vs[k * 256 + f * 4]);
            acc[k] = fmaf(xv.x, vv.x, fmaf(xv.y, vv.y,
                     fmaf(xv.z, vv.z, fmaf(xv.w, vv.w, acc[k]))));
        }
    }
    #pragma unroll 4
    for (int f = 0; f < 32; f++) {
        float4 xv = xb[f];
        #pragma unroll
        for (int k = 0; k < KK; k++) {
            float4 vv = *(const float4*)(&Vs[k * 256 + 128 + f * 4]);
            acc[k] = fmaf(xv.x, vv.x, fmaf(xv.y, vv.y,
                     fmaf(xv.z, vv.z, fmaf(xv.w, vv.w, acc[k]))));
        }
    }
    #pragma unroll
    for (int k = 0; k < KK; k++) gP2[(size_t)n * KK + k] = acc[k];
}

// ---------------- main kernel ----------------
__global__ __launch_bounds__(256, 2)
void ntn_main(float* __restrict__ out) {
    __shared__ float sred[3 * 256];           // sdot/sn1/sn2 [2 wn][128 rows]
    const int tid  = threadIdx.x;
    const int lane = tid & 31;
    const int w    = tid >> 5;
    const int wm   = w & 3;        // rows 32*wm .. +31 (of 128)
    const int wn   = w >> 2;       // 16-col group within each 32-col e-pass
    const int k     = blockIdx.y;
    const int rbase = blockIdx.x * 128;
    const int rtb   = blockIdx.x * 8 + wm * 2;

    float* sdot = sred;
    float* sn1  = sred + 256;
    float* sn2  = sred + 512;

    float dv[4]  = {0.f, 0.f, 0.f, 0.f};
    float n1v[4] = {0.f, 0.f, 0.f, 0.f};
    float n2v[4] = {0.f, 0.f, 0.f, 0.f};

    #pragma unroll 1
    for (int p = 0; p < 4; p++) {
        const int nt0 = p * 4 + wn * 2;       // two n8-tiles: nt0, nt0+1
        int chh[2][2][2][4], ccr[2][2][2][4]; // [g][mt][nt][4]
        #pragma unroll
        for (int g = 0; g < 2; g++)
            #pragma unroll
            for (int mt = 0; mt < 2; mt++)
                #pragma unroll
                for (int nt = 0; nt < 2; nt++)
                    #pragma unroll
                    for (int q = 0; q < 4; q++) {
                        chh[g][mt][nt][q] = 0;
                        ccr[g][mt][nt][q] = 0;
                    }

        #pragma unroll
        for (int kt = 0; kt < 4; kt++) {
            #pragma unroll
            for (int g = 0; g < 2; g++) {
                uint4 ah0 = gXq[g][0][rtb][kt][lane];
                uint4 ah1 = gXq[g][0][rtb + 1][kt][lane];
                uint4 al0 = gXq[g][1][rtb][kt][lane];
                uint4 al1 = gXq[g][1][rtb + 1][kt][lane];
                uint2 bh0 = gWq[k][g][0][kt][nt0][lane];
                uint2 bh1 = gWq[k][g][0][kt][nt0 + 1][lane];
                uint2 bl0 = gWq[k][g][1][kt][nt0][lane];
                uint2 bl1 = gWq[k][g][1][kt][nt0 + 1][lane];
                // hh
                IMMA(chh[g][0][0], ah0, bh0);  IMMA(chh[g][1][0], ah1, bh0);
                IMMA(chh[g][0][1], ah0, bh1);  IMMA(chh[g][1][1], ah1, bh1);
                // cross: hl + lh (shared accumulator)
                IMMA(ccr[g][0][0], ah0, bl0);  IMMA(ccr[g][1][0], ah1, bl0);
                IMMA(ccr[g][0][1], ah0, bl1);  IMMA(ccr[g][1][1], ah1, bl1);
                IMMA(ccr[g][0][0], al0, bh0);  IMMA(ccr[g][1][0], al1, bh0);
                IMMA(ccr[g][0][1], al0, bh1);  IMMA(ccr[g][1][1], al1, bh1);
            }
        }

        // fold this e-pass: v = hh*2^14 + cross*2^7 (exact in fp32)
        #pragma unroll
        for (int mt = 0; mt < 2; mt++)
            #pragma unroll
            for (int nt = 0; nt < 2; nt++) {
                float v1[4], v2[4];
                #pragma unroll
                for (int q = 0; q < 4; q++) {
                    v1[q] = fmaf((float)chh[0][mt][nt][q], 16384.f,
                                 (float)ccr[0][mt][nt][q] * 128.f);
                    v2[q] = fmaf((float)chh[1][mt][nt][q], 16384.f,
                                 (float)ccr[1][mt][nt][q] * 128.f);
                }
                const int s0 = mt * 2;
                dv[s0]      = fmaf(v1[0], v2[0], fmaf(v1[1], v2[1], dv[s0]));
                n1v[s0]     = fmaf(v1[0], v1[0], fmaf(v1[1], v1[1], n1v[s0]));
                n2v[s0]     = fmaf(v2[0], v2[0], fmaf(v2[1], v2[1], n2v[s0]));
                dv[s0 + 1]  = fmaf(v1[2], v2[2], fmaf(v1[3], v2[3], dv[s0 + 1]));
                n1v[s0 + 1] = fmaf(v1[2], v1[2], fmaf(v1[3], v1[3], n1v[s0 + 1]));
                n2v[s0 + 1] = fmaf(v2[2], v2[2], fmaf(v2[3], v2[3], n2v[s0 + 1]));
            }
    }

    // ---- reduce across the 4 lanes sharing a row ----
    #pragma unroll
    for (int s = 0; s < 4; s++) {
        #pragma unroll
        for (int off = 1; off <= 2; off <<= 1) {
            dv[s]  += __shfl_xor_sync(0xffffffffu, dv[s],  off);
            n1v[s] += __shfl_xor_sync(0xffffffffu, n1v[s], off);
            n2v[s] += __shfl_xor_sync(0xffffffffu, n2v[s], off);
        }
    }
    if ((lane & 3) == 0) {
        #pragma unroll
        for (int s = 0; s < 4; s++) {
            const int row = wm * 32 + (s >> 1) * 16 + (s & 1) * 8 + (lane >> 2);
            sdot[wn * 128 + row] = dv[s];
            sn1[wn * 128 + row]  = n1v[s];
            sn2[wn * 128 + row]  = n2v[s];
        }
    }
    __syncthreads();

    // ---- epilogue: scales cancel in cosine; part2/bias from gP2 ----
    if (tid < 128) {
        const int row = tid;
        float dot = sdot[row] + sdot[128 + row];
        float nn1 = sn1[row]  + sn1[128 + row];
        float nn2 = sn2[row]  + sn2[128 + row];
        float s1 = fmaxf(sqrtf(nn1), EPSN);
        float s2 = fmaxf(sqrtf(nn2), EPSN);
        float v = dot / (s1 * s2) + gP2[(size_t)(rbase + row) * KK + k];
        out[(size_t)(rbase + row) * KK + k] = fmaxf(v, 0.f);
    }
}

extern "C" void kernel_launch(void* const* d_in, const int* in_sizes, int n_in,
                              void* d_out, int out_size) {
    const float* x1 = (const float*)d_in[0];
    const float* x2 = (const float*)d_in[1];
    const float* W1 = (const float*)d_in[2];
    const float* W2 = (const float*)d_in[3];
    const float* V  = (const float*)d_in[4];
    const float* b  = (const float*)d_in[5];
    float* out = (float*)d_out;

    prep_x<<<512, 256>>>(x1, x2);
    prep_w<<<64, 256>>>(W1, W2);
    prep_p2<<<NN / 256, 256>>>(x1, x2, V, b);

    dim3 grid(NN / 128, KK);
    ntn_main<<<grid, 256>>>(out);
}

// round 9
// speedup vs baseline: 3.3982x; 3.3982x over previous
#include <cuda_runtime.h>
#include <cuda_fp16.h>
#include <cstdint>

// NTN: out[n,k] = relu( cos(x1@W1[k], x2@W2[k]) + [x1,x2]@V[k] + b[k] )
// R9: R8 with prep_w index-decode bug fixed (bit-10 skip / k truncated to 4
// bits). fp16 HMMA asymmetric split: A = fp16(X), B = W hi + lo*2^11.
// 2 products per tile; 4x32-col e-chunks double-buffered; 2 CTAs/SM.

#define NN 32768
#define DD 128
#define KK 32
#define EPSN 1e-8f
#define INV2048 4.8828125e-4f

// ---------------- global scratch ----------------
__device__ uint4 gXfrag[2][2048][8][32];   // [mat][rowtile16][ds][lane] fp16 A-frags
__device__ uint4 gWq[32][4][2048];         // [k][chunk][granule] fp16 W planes
__device__ float gP2[(size_t)NN * KK];     // part2 + bias

// ---------------- helpers ----------------
static __device__ __forceinline__ uint32_t s2u(const void* p) {
    uint32_t a;
    asm("{ .reg .u64 t; cvta.to.shared.u64 t, %1; cvt.u32.u64 %0, t; }"
        : "=r"(a) : "l"(p));
    return a;
}
static __device__ __forceinline__ uint32_t packh2(float a, float b) {
    __half2 h = __floats2half2_rn(a, b);
    return *reinterpret_cast<uint32_t*>(&h);
}

#define LDSM4T(R, addr)                                                         \
    asm volatile("ldmatrix.sync.aligned.m8n8.x4.trans.shared.b16 {%0,%1,%2,%3},[%4];" \
                 : "=r"((R)[0]), "=r"((R)[1]), "=r"((R)[2]), "=r"((R)[3])       \
                 : "r"(addr))

#define HMMA(C, A, B0, B1)                                                      \
    asm volatile("mma.sync.aligned.m16n8k16.row.col.f32.f16.f16.f32 "           \
                 "{%0,%1,%2,%3},{%4,%5,%6,%7},{%8,%9},{%0,%1,%2,%3};"           \
                 : "+f"((C)[0]), "+f"((C)[1]), "+f"((C)[2]), "+f"((C)[3])       \
                 : "r"((A).x), "r"((A).y), "r"((A).z), "r"((A).w),              \
                   "r"(B0), "r"(B1))

static __device__ __forceinline__ void cp16(uint32_t dst, const void* src) {
    asm volatile("cp.async.cg.shared.global [%0], [%1], 16;"
                 :: "r"(dst), "l"(src) : "memory");
}
static __device__ __forceinline__ void cp_commit() {
    asm volatile("cp.async.commit_group;" ::: "memory");
}
template <int N>
static __device__ __forceinline__ void cp_wait() {
    asm volatile("cp.async.wait_group %0;" :: "n"(N) : "memory");
}

// ---------------- prep: X -> fp16 A-fragments ----------------
__global__ __launch_bounds__(256) void prep_x(const float* __restrict__ x1,
                                              const float* __restrict__ x2) {
    int wid  = (blockIdx.x * 256 + threadIdx.x) >> 5;   // 0..4095
    int lane = threadIdx.x & 31;
    int m  = wid >> 11;
    int rt = wid & 2047;
    const float* x = m ? x2 : x1;
    const float* p0 = x + (size_t)(rt * 16 + (lane >> 2)) * DD;
    const float* p1 = p0 + 8 * DD;
    const int c0 = (lane & 3) * 2;
    #pragma unroll
    for (int ds = 0; ds < 8; ds++) {
        int c = ds * 16 + c0;
        float2 v0 = *(const float2*)(p0 + c);
        float2 v1 = *(const float2*)(p1 + c);
        float2 v2 = *(const float2*)(p0 + c + 8);
        float2 v3 = *(const float2*)(p1 + c + 8);
        gXfrag[m][rt][ds][lane] = make_uint4(packh2(v0.x, v0.y), packh2(v1.x, v1.y),
                                             packh2(v2.x, v2.y), packh2(v3.x, v3.y));
    }
}

// ---------------- prep: W -> fp16 hi + lo*2^11 granules ----------------
// t bits: e8:0-1, d:2-8, mat:9, ch:10-11, k:12-16  (131072 threads total)
__global__ __launch_bounds__(256) void prep_w(const float* __restrict__ W1,
                                              const float* __restrict__ W2) {
    int t   = blockIdx.x * 256 + threadIdx.x;   // 0..131071
    int e8  = t & 3;
    int d   = (t >> 2) & 127;
    int mat = (t >> 9) & 1;
    int ch  = (t >> 10) & 3;
    int k   = t >> 12;
    const float* w = (mat ? W2 : W1) + (size_t)k * DD * DD + (size_t)d * DD
                   + ch * 32 + e8 * 8;
    uint32_t hh[4], ll[4];
    #pragma unroll
    for (int j = 0; j < 4; j++) {
        float a = w[2 * j], b = w[2 * j + 1];
        __half ha = __float2half_rn(a), hb = __float2half_rn(b);
        float ra = (a - __half2float(ha)) * 2048.f;
        float rb = (b - __half2float(hb)) * 2048.f;
        hh[j] = (uint32_t)__half_as_ushort(ha)
              | ((uint32_t)__half_as_ushort(hb) << 16);
        ll[j] = packh2(ra, rb);
    }
    gWq[k][ch][(mat * 2 + 0) * 512 + d * 4 + e8] = make_uint4(hh[0], hh[1], hh[2], hh[3]);
    gWq[k][ch][(mat * 2 + 1) * 512 + d * 4 + e8] = make_uint4(ll[0], ll[1], ll[2], ll[3]);
}

// ---------------- prep: part2 + bias (exact fp32) ----------------
__global__ __launch_bounds__(256) void prep_p2(const float* __restrict__ x1,
                                               const float* __restrict__ x2,
                                               const float* __restrict__ Vg,
                                               const float* __restrict__ bg) {
    __shared__ float Vs[KK * 256];
    __shared__ float bs[KK];
    int tid = threadIdx.x;
    for (int i = tid; i < KK * 256; i += 256) Vs[i] = Vg[i];
    if (tid < KK) bs[tid] = bg[tid];
    __syncthreads();
    int n = blockIdx.x * 256 + tid;
    float acc[KK];
    #pragma unroll
    for (int k = 0; k < KK; k++) acc[k] = bs[k];
    const float4* xa = (const float4*)(x1 + (size_t)n * DD);
    const float4* xb = (const float4*)(x2 + (size_t)n * DD);
    #pragma unroll 4
    for (int f = 0; f < 32; f++) {
        float4 xv = xa[f];
        #pragma unroll
        for (int k = 0; k < KK; k++) {
            float4 vv = *(const float4*)(&Vs[k * 256 + f * 4]);
            acc[k] = fmaf(xv.x, vv.x, fmaf(xv.y, vv.y,
                     fmaf(xv.z, vv.z, fmaf(xv.w, vv.w, acc[k]))));
        }
    }
    #pragma unroll 4
    for (int f = 0; f < 32; f++) {
        float4 xv = xb[f];
        #pragma unroll
        for (int k = 0; k < KK; k++) {
            float4 vv = *(const float4*)(&Vs[k * 256 + 128 + f * 4]);
            acc[k] = fmaf(xv.x, vv.x, fmaf(xv.y, vv.y,
                     fmaf(xv.z, vv.z, fmaf(xv.w, vv.w, acc[k]))));
        }
    }
    #pragma unroll
    for (int k = 0; k < KK; k++) gP2[(size_t)n * KK + k] = acc[k];
}

// ---------------- main kernel ----------------
#define WROWB 80                     // 64B data + 16B pad
#define WPL   (128 * WROWB)          // 10240 per (mat,plane) tile
#define CHUNKB (4 * WPL)             // 40960 per chunk
#define OFF_RED (2 * CHUNKB)         // 81920
#define SMEM_MAIN (OFF_RED + 3072)   // 84992

__global__ __launch_bounds__(256, 2)
void ntn_main(float* __restrict__ out) {
    extern __shared__ char smem[];
    const uint32_t sb = s2u(smem);
    const int tid  = threadIdx.x;
    const int lane = tid & 31;
    const int w    = tid >> 5;
    const int wm   = w & 3;        // rows 32*wm .. +31 (of 128)
    const int wn   = w >> 2;       // 16-col half within each 32-col chunk
    const int k     = blockIdx.y;
    const int rbase = blockIdx.x * 128;
    const int rtb   = blockIdx.x * 8 + wm * 2;

    float* sdot = (float*)(smem + OFF_RED);
    float* sn1  = sdot + 256;
    float* sn2  = sn1 + 256;

    // ---- cp.async chunk 0 ----
    #pragma unroll
    for (int i = 0; i < 8; i++) {
        int idx = tid + 256 * i;               // 0..2047
        int mp  = idx >> 9;
        int d   = (idx >> 2) & 127;
        int e8  = idx & 3;
        cp16(sb + mp * WPL + d * WROWB + e8 * 16, &gWq[k][0][idx]);
    }
    cp_commit();

    const int arow  = (lane & 7) + ((lane >> 3) & 1) * 8;
    const int half8 = lane >> 4;
    const uint32_t boff = (uint32_t)(arow * WROWB + wn * 32 + half8 * 16);

    // ---- A register double-buffer: prefetch step 0 ----
    uint4 ah[2][2];
    ah[0][0] = gXfrag[0][rtb][0][lane];
    ah[0][1] = gXfrag[0][rtb + 1][0][lane];

    float dv[4]  = {0.f, 0.f, 0.f, 0.f};
    float n1v[4] = {0.f, 0.f, 0.f, 0.f};
    float n2v[4] = {0.f, 0.f, 0.f, 0.f};

    cp_wait<0>();
    __syncthreads();

    #pragma unroll 1
    for (int c = 0; c < 4; c++) {
        const uint32_t cbuf = sb + (c & 1) * CHUNKB;
        if (c < 3) {
            const uint32_t nbuf = sb + ((c + 1) & 1) * CHUNKB;
            #pragma unroll
            for (int i = 0; i < 8; i++) {
                int idx = tid + 256 * i;
                int mp  = idx >> 9;
                int d   = (idx >> 2) & 127;
                int e8  = idx & 3;
                cp16(nbuf + mp * WPL + d * WROWB + e8 * 16, &gWq[k][c + 1][idx]);
            }
            cp_commit();
        }

        float chh[2][2][2][4], chl[2][2][2][4];   // [g][mt][nt][q]
        #pragma unroll
        for (int g = 0; g < 2; g++)
            #pragma unroll
            for (int mt = 0; mt < 2; mt++)
                #pragma unroll
                for (int nt = 0; nt < 2; nt++)
                    #pragma unroll
                    for (int q = 0; q < 4; q++) {
                        chh[g][mt][nt][q] = 0.f;
                        chl[g][mt][nt][q] = 0.f;
                    }

        #pragma unroll
        for (int step = 0; step < 16; step++) {
            const int cur = step & 1, nxt = cur ^ 1;
            const int ds = step >> 1, g = step & 1;
            {   // prefetch next step's A (wraps; A independent of chunk)
                const int ns = (step + 1) & 15;
                const int nds = ns >> 1, ng = ns & 1;
                ah[nxt][0] = gXfrag[ng][rtb][nds][lane];
                ah[nxt][1] = gXfrag[ng][rtb + 1][nds][lane];
            }
            uint32_t bh[4], bl[4];
            const uint32_t tile = cbuf + (g * 2) * WPL + (uint32_t)(ds * 16 * WROWB) + boff;
            LDSM4T(bh, tile);
            LDSM4T(bl, tile + WPL);
            #pragma unroll
            for (int nt = 0; nt < 2; nt++) {
                HMMA(chh[g][0][nt], ah[cur][0], bh[nt * 2], bh[nt * 2 + 1]);
                HMMA(chh[g][1][nt], ah[cur][1], bh[nt * 2], bh[nt * 2 + 1]);
                HMMA(chl[g][0][nt], ah[cur][0], bl[nt * 2], bl[nt * 2 + 1]);
                HMMA(chl[g][1][nt], ah[cur][1], bl[nt * 2], bl[nt * 2 + 1]);
            }
        }

        // ---- fold chunk into per-row reductions (registers) ----
        #pragma unroll
        for (int mt = 0; mt < 2; mt++)
            #pragma unroll
            for (int nt = 0; nt < 2; nt++) {
                float v1[4], v2[4];
                #pragma unroll
                for (int q = 0; q < 4; q++) {
                    v1[q] = fmaf(chl[0][mt][nt][q], INV2048, chh[0][mt][nt][q]);
                    v2[q] = fmaf(chl[1][mt][nt][q], INV2048, chh[1][mt][nt][q]);
                }
                const int s0 = mt * 2;
                dv[s0]      = fmaf(v1[0], v2[0], fmaf(v1[1], v2[1], dv[s0]));
                n1v[s0]     = fmaf(v1[0], v1[0], fmaf(v1[1], v1[1], n1v[s0]));
                n2v[s0]     = fmaf(v2[0], v2[0], fmaf(v2[1], v2[1], n2v[s0]));
                dv[s0 + 1]  = fmaf(v1[2], v2[2], fmaf(v1[3], v2[3], dv[s0 + 1]));
                n1v[s0 + 1] = fmaf(v1[2], v1[2], fmaf(v1[3], v1[3], n1v[s0 + 1]));
                n2v[s0 + 1] = fmaf(v2[2], v2[2], fmaf(v2[3], v2[3], n2v[s0 + 1]));
            }

        cp_wait<0>();
        __syncthreads();
    }

    // ---- lane reduce (4 lanes share a row) + stage per-wn partials ----
    #pragma unroll
    for (int s = 0; s < 4; s++) {
        #pragma unroll
        for (int off = 1; off <= 2; off <<= 1) {
            dv[s]  += __shfl_xor_sync(0xffffffffu, dv[s],  off);
            n1v[s] += __shfl_xor_sync(0xffffffffu, n1v[s], off);
            n2v[s] += __shfl_xor_sync(0xffffffffu, n2v[s], off);
        }
    }
    if ((lane & 3) == 0) {
        #pragma unroll
        for (int s = 0; s < 4; s++) {
            const int row = wm * 32 + (s >> 1) * 16 + (s & 1) * 8 + (lane >> 2);
            sdot[wn * 128 + row] = dv[s];
            sn1[wn * 128 + row]  = n1v[s];
            sn2[wn * 128 + row]  = n2v[s];
        }
    }
    __syncthreads();

    // ---- epilogue ----
    if (tid < 128) {
        const int row = tid;
        float dot = sdot[row] + sdot[128 + row];
        float nn1 = sn1[row]  + sn1[128 + row];
        float nn2 = sn2[row]  + sn2[128 + row];
        float s1 = fmaxf(sqrtf(nn1), EPSN);
        float s2 = fmaxf(sqrtf(nn2), EPSN);
        float v = dot / (s1 * s2) + gP2[(size_t)(rbase + row) * KK + k];
        out[(size_t)(rbase + row) * KK + k] = fmaxf(v, 0.f);
    }
}

extern "C" void kernel_launch(void* const* d_in, const int* in_sizes, int n_in,
                              void* d_out, int out_size) {
    const float* x1 = (const float*)d_in[0];
    const float* x2 = (const float*)d_in[1];
    const float* W1 = (const float*)d_in[2];
    const float* W2 = (const float*)d_in[3];
    const float* V  = (const float*)d_in[4];
    const float* b  = (const float*)d_in[5];
    float* out = (float*)d_out;

    prep_x<<<512, 256>>>(x1, x2);
    prep_w<<<512, 256>>>(W1, W2);
    prep_p2<<<NN / 256, 256>>>(x1, x2, V, b);

    cudaFuncSetAttribute(ntn_main,
                         cudaFuncAttributeMaxDynamicSharedMemorySize, SMEM_MAIN);
    dim3 grid(NN / 128, KK);
    ntn_main<<<grid, 256, SMEM_MAIN>>>(out);
}

// round 10
// speedup vs baseline: 5.9810x; 1.7600x over previous
#include <cuda_runtime.h>
#include <cuda_fp16.h>
#include <cstdint>

// NTN: out[n,k] = relu( cos(x1@W1[k], x2@W2[k]) + [x1,x2]@V[k] + b[k] )
// R10: pure fp16 HMMA (1 product per tile). A fragment-major global, W single
// fp16 plane, 2x64-col e-chunks double-buffered, 2 CTAs/SM. fp32 epilogue.

#define NN 32768
#define DD 128
#define KK 32
#define EPSN 1e-8f

// ---------------- global scratch ----------------
__device__ uint4 gXfrag[2][2048][8][32];   // [mat][rowtile16][ds][lane] fp16 A-frags
__device__ uint4 gWh[32][2][2048];         // [k][chunk][granule] fp16 W (single plane)
__device__ float gP2[(size_t)NN * KK];     // part2 + bias

// ---------------- helpers ----------------
static __device__ __forceinline__ uint32_t s2u(const void* p) {
    uint32_t a;
    asm("{ .reg .u64 t; cvta.to.shared.u64 t, %1; cvt.u32.u64 %0, t; }"
        : "=r"(a) : "l"(p));
    return a;
}
static __device__ __forceinline__ uint32_t packh2(float a, float b) {
    __half2 h = __floats2half2_rn(a, b);
    return *reinterpret_cast<uint32_t*>(&h);
}

#define LDSM4T(R, addr)                                                         \
    asm volatile("ldmatrix.sync.aligned.m8n8.x4.trans.shared.b16 {%0,%1,%2,%3},[%4];" \
                 : "=r"((R)[0]), "=r"((R)[1]), "=r"((R)[2]), "=r"((R)[3])       \
                 : "r"(addr))

#define HMMA(C, A, B0, B1)                                                      \
    asm volatile("mma.sync.aligned.m16n8k16.row.col.f32.f16.f16.f32 "           \
                 "{%0,%1,%2,%3},{%4,%5,%6,%7},{%8,%9},{%0,%1,%2,%3};"           \
                 : "+f"((C)[0]), "+f"((C)[1]), "+f"((C)[2]), "+f"((C)[3])       \
                 : "r"((A).x), "r"((A).y), "r"((A).z), "r"((A).w),              \
                   "r"(B0), "r"(B1))

static __device__ __forceinline__ void cp16(uint32_t dst, const void* src) {
    asm volatile("cp.async.cg.shared.global [%0], [%1], 16;"
                 :: "r"(dst), "l"(src) : "memory");
}
static __device__ __forceinline__ void cp_commit() {
    asm volatile("cp.async.commit_group;" ::: "memory");
}
template <int N>
static __device__ __forceinline__ void cp_wait() {
    asm volatile("cp.async.wait_group %0;" :: "n"(N) : "memory");
}

// ---------------- prep: X -> fp16 A-fragments ----------------
__global__ __launch_bounds__(256) void prep_x(const float* __restrict__ x1,
                                              const float* __restrict__ x2) {
    int wid  = (blockIdx.x * 256 + threadIdx.x) >> 5;   // 0..4095
    int lane = threadIdx.x & 31;
    int m  = wid >> 11;
    int rt = wid & 2047;
    const float* x = m ? x2 : x1;
    const float* p0 = x + (size_t)(rt * 16 + (lane >> 2)) * DD;
    const float* p1 = p0 + 8 * DD;
    const int c0 = (lane & 3) * 2;
    #pragma unroll
    for (int ds = 0; ds < 8; ds++) {
        int c = ds * 16 + c0;
        float2 v0 = *(const float2*)(p0 + c);
        float2 v1 = *(const float2*)(p1 + c);
        float2 v2 = *(const float2*)(p0 + c + 8);
        float2 v3 = *(const float2*)(p1 + c + 8);
        gXfrag[m][rt][ds][lane] = make_uint4(packh2(v0.x, v0.y), packh2(v1.x, v1.y),
                                             packh2(v2.x, v2.y), packh2(v3.x, v3.y));
    }
}

// ---------------- prep: W -> fp16 granules ----------------
// t bits: e8:0-2, d:3-9, mat:10, ch:11, k:12-16  (131072 threads)
// granule idx within [k][ch]: mat*1024 + d*8 + e8
__global__ __launch_bounds__(256) void prep_w(const float* __restrict__ W1,
                                              const float* __restrict__ W2) {
    int t   = blockIdx.x * 256 + threadIdx.x;   // 0..131071
    int e8  = t & 7;
    int d   = (t >> 3) & 127;
    int mat = (t >> 10) & 1;
    int ch  = (t >> 11) & 1;
    int k   = t >> 12;
    const float* w = (mat ? W2 : W1) + (size_t)k * DD * DD + (size_t)d * DD
                   + ch * 64 + e8 * 8;
    uint32_t hh[4];
    #pragma unroll
    for (int j = 0; j < 4; j++) hh[j] = packh2(w[2 * j], w[2 * j + 1]);
    gWh[k][ch][mat * 1024 + d * 8 + e8] = make_uint4(hh[0], hh[1], hh[2], hh[3]);
}

// ---------------- prep: part2 + bias (exact fp32) ----------------
__global__ __launch_bounds__(256) void prep_p2(const float* __restrict__ x1,
                                               const float* __restrict__ x2,
                                               const float* __restrict__ Vg,
                                               const float* __restrict__ bg) {
    __shared__ float Vs[KK * 256];
    __shared__ float bs[KK];
    int tid = threadIdx.x;
    for (int i = tid; i < KK * 256; i += 256) Vs[i] = Vg[i];
    if (tid < KK) bs[tid] = bg[tid];
    __syncthreads();
    int n = blockIdx.x * 256 + tid;
    float acc[KK];
    #pragma unroll
    for (int k = 0; k < KK; k++) acc[k] = bs[k];
    const float4* xa = (const float4*)(x1 + (size_t)n * DD);
    const float4* xb = (const float4*)(x2 + (size_t)n * DD);
    #pragma unroll 4
    for (int f = 0; f < 32; f++) {
        float4 xv = xa[f];
        #pragma unroll
        for (int k = 0; k < KK; k++) {
            float4 vv = *(const float4*)(&Vs[k * 256 + f * 4]);
            acc[k] = fmaf(xv.x, vv.x, fmaf(xv.y, vv.y,
                     fmaf(xv.z, vv.z, fmaf(xv.w, vv.w, acc[k]))));
        }
    }
    #pragma unroll 4
    for (int f = 0; f < 32; f++) {
        float4 xv = xb[f];
        #pragma unroll
        for (int k = 0; k < KK; k++) {
            float4 vv = *(const float4*)(&Vs[k * 256 + 128 + f * 4]);
            acc[k] = fmaf(xv.x, vv.x, fmaf(xv.y, vv.y,
                     fmaf(xv.z, vv.z, fmaf(xv.w, vv.w, acc[k]))));
        }
    }
    #pragma unroll
    for (int k = 0; k < KK; k++) gP2[(size_t)n * KK + k] = acc[k];
}

// ---------------- main kernel ----------------
#define WROWB 144                    // 128B data (64 fp16) + 16B pad
#define WPL   (128 * WROWB)          // 18432 per mat tile
#define CHUNKB (2 * WPL)             // 36864 per chunk (2 mats)
#define OFF_RED (2 * CHUNKB)         // 73728
#define SMEM_MAIN (OFF_RED + 3072)   // 76800

__global__ __launch_bounds__(256, 2)
void ntn_main(float* __restrict__ out) {
    extern __shared__ char smem[];
    const uint32_t sb = s2u(smem);
    const int tid  = threadIdx.x;
    const int lane = tid & 31;
    const int w    = tid >> 5;
    const int wm   = w & 3;        // rows 32*wm .. +31 (of 128)
    const int wn   = w >> 2;       // 32-col half within each 64-col chunk
    const int k     = blockIdx.y;
    const int rbase = blockIdx.x * 128;
    const int rtb   = blockIdx.x * 8 + wm * 2;

    float* sdot = (float*)(smem + OFF_RED);
    float* sn1  = sdot + 256;
    float* sn2  = sn1 + 256;

    // ---- cp.async chunk 0 (2048 granules) ----
    #pragma unroll
    for (int i = 0; i < 8; i++) {
        int idx = tid + 256 * i;               // 0..2047
        int mp  = idx >> 10;
        int d   = (idx >> 3) & 127;
        int e8  = idx & 7;
        cp16(sb + mp * WPL + d * WROWB + e8 * 16, &gWh[k][0][idx]);
    }
    cp_commit();

    const int arow  = (lane & 7) + ((lane >> 3) & 1) * 8;
    const int half8 = lane >> 4;
    const uint32_t boff = (uint32_t)(arow * WROWB + wn * 64 + half8 * 16);

    // ---- A register double-buffer: prefetch step 0 ----
    uint4 ah[2][2];
    ah[0][0] = gXfrag[0][rtb][0][lane];
    ah[0][1] = gXfrag[0][rtb + 1][0][lane];

    float dv[4]  = {0.f, 0.f, 0.f, 0.f};
    float n1v[4] = {0.f, 0.f, 0.f, 0.f};
    float n2v[4] = {0.f, 0.f, 0.f, 0.f};

    cp_wait<0>();
    __syncthreads();

    #pragma unroll 1
    for (int c = 0; c < 2; c++) {
        const uint32_t cbuf = sb + (c & 1) * CHUNKB;
        if (c < 1) {
            const uint32_t nbuf = sb + CHUNKB;
            #pragma unroll
            for (int i = 0; i < 8; i++) {
                int idx = tid + 256 * i;
                int mp  = idx >> 10;
                int d   = (idx >> 3) & 127;
                int e8  = idx & 7;
                cp16(nbuf + mp * WPL + d * WROWB + e8 * 16, &gWh[k][1][idx]);
            }
            cp_commit();
        }

        float c1[2][4][4], c2[2][4][4];     // [mt][nt][q], g in {0:c1, 1:c2}
        #pragma unroll
        for (int mt = 0; mt < 2; mt++)
            #pragma unroll
            for (int nt = 0; nt < 4; nt++)
                #pragma unroll
                for (int q = 0; q < 4; q++) { c1[mt][nt][q] = 0.f; c2[mt][nt][q] = 0.f; }

        #pragma unroll
        for (int step = 0; step < 16; step++) {
            const int cur = step & 1, nxt = cur ^ 1;
            const int ds = step >> 1, g = step & 1;
            {   // prefetch next step's A (wraps; A independent of chunk)
                const int ns = (step + 1) & 15;
                const int nds = ns >> 1, ng = ns & 1;
                ah[nxt][0] = gXfrag[ng][rtb][nds][lane];
                ah[nxt][1] = gXfrag[ng][rtb + 1][nds][lane];
            }
            uint32_t b0[4], b1[4];
            const uint32_t tile = cbuf + g * WPL + (uint32_t)(ds * 16 * WROWB) + boff;
            LDSM4T(b0, tile);          // cols wn*32 .. +15
            LDSM4T(b1, tile + 32);     // cols wn*32+16 .. +31
            float (*cc)[4][4] = g ? c2 : c1;
            #pragma unroll
            for (int nt = 0; nt < 2; nt++) {
                HMMA(cc[0][nt],     ah[cur][0], b0[nt * 2], b0[nt * 2 + 1]);
                HMMA(cc[1][nt],     ah[cur][1], b0[nt * 2], b0[nt * 2 + 1]);
                HMMA(cc[0][nt + 2], ah[cur][0], b1[nt * 2], b1[nt * 2 + 1]);
                HMMA(cc[1][nt + 2], ah[cur][1], b1[nt * 2], b1[nt * 2 + 1]);
            }
        }

        // ---- fold chunk into per-row reductions ----
        #pragma unroll
        for (int mt = 0; mt < 2; mt++)
            #pragma unroll
            for (int nt = 0; nt < 4; nt++) {
                const int s0 = mt * 2;
                float a0 = c1[mt][nt][0], b0f = c2[mt][nt][0];
                float a1 = c1[mt][nt][1], b1f = c2[mt][nt][1];
                float a2 = c1[mt][nt][2], b2f = c2[mt][nt][2];
                float a3 = c1[mt][nt][3], b3f = c2[mt][nt][3];
                dv[s0]      = fmaf(a0, b0f, fmaf(a1, b1f, dv[s0]));
                n1v[s0]     = fmaf(a0, a0, fmaf(a1, a1, n1v[s0]));
                n2v[s0]     = fmaf(b0f, b0f, fmaf(b1f, b1f, n2v[s0]));
                dv[s0 + 1]  = fmaf(a2, b2f, fmaf(a3, b3f, dv[s0 + 1]));
                n1v[s0 + 1] = fmaf(a2, a2, fmaf(a3, a3, n1v[s0 + 1]));
                n2v[s0 + 1] = fmaf(b2f, b2f, fmaf(b3f, b3f, n2v[s0 + 1]));
            }

        cp_wait<0>();
        __syncthreads();
    }

    // ---- lane reduce (4 lanes share a row) + stage per-wn partials ----
    #pragma unroll
    for (int s = 0; s < 4; s++) {
        #pragma unroll
        for (int off = 1; off <= 2; off <<= 1) {
            dv[s]  += __shfl_xor_sync(0xffffffffu, dv[s],  off);
            n1v[s] += __shfl_xor_sync(0xffffffffu, n1v[s], off);
            n2v[s] += __shfl_xor_sync(0xffffffffu, n2v[s], off);
        }
    }
    if ((lane & 3) == 0) {
        #pragma unroll
        for (int s = 0; s < 4; s++) {
            const int row = wm * 32 + (s >> 1) * 16 + (s & 1) * 8 + (lane >> 2);
            sdot[wn * 128 + row] = dv[s];
            sn1[wn * 128 + row]  = n1v[s];
            sn2[wn * 128 + row]  = n2v[s];
        }
    }
    __syncthreads();

    // ---- epilogue ----
    if (tid < 128) {
        const int row = tid;
        float dot = sdot[row] + sdot[128 + row];
        float nn1 = sn1[row]  + sn1[128 + row];
        float nn2 = sn2[row]  + sn2[128 + row];
        float s1 = fmaxf(sqrtf(nn1), EPSN);
        float s2 = fmaxf(sqrtf(nn2), EPSN);
        float v = dot / (s1 * s2) + gP2[(size_t)(rbase + row) * KK + k];
        out[(size_t)(rbase + row) * KK + k] = fmaxf(v, 0.f);
    }
}

extern "C" void kernel_launch(void* const* d_in, const int* in_sizes, int n_in,
                              void* d_out, int out_size) {
    const float* x1 = (const float*)d_in[0];
    const float* x2 = (const float*)d_in[1];
    const float* W1 = (const float*)d_in[2];
    const float* W2 = (const float*)d_in[3];
    const float* V  = (const float*)d_in[4];
    const float* b  = (const float*)d_in[5];
    float* out = (float*)d_out;

    prep_x<<<512, 256>>>(x1, x2);
    prep_w<<<512, 256>>>(W1, W2);
    prep_p2<<<NN / 256, 256>>>(x1, x2, V, b);

    cudaFuncSetAttribute(ntn_main,
                         cudaFuncAttributeMaxDynamicSharedMemorySize, SMEM_MAIN);
    dim3 grid(NN / 128, KK);
    ntn_main<<<grid, 256, SMEM_MAIN>>>(out);
}

// round 11
// speedup vs baseline: 6.6574x; 1.1131x over previous
#include <cuda_runtime.h>
#include <cuda_fp16.h>
#include <cstdint>

// NTN: out[n,k] = relu( cos(x1@W1[k], x2@W2[k]) + [x1,x2]@V[k] + b[k] )
// R11: pure fp16 HMMA, warp tile 32x64 (nt=8), g-split with fp16 smem staging
// of x1t. 2 A-LDG + 4 LDSM per 16 HMMA (1.5 wf/HMMA). CTA = 256 rows x 1 k,
// both W chunks loaded upfront, warp-private fold, direct output writes.

#define NN 32768
#define DD 128
#define KK 32
#define EPSN 1e-8f

// ---------------- global scratch ----------------
__device__ uint4 gXfrag[2][2048][8][32];   // [mat][rowtile16][ds][lane] fp16 A-frags
__device__ uint4 gWh[32][2][2048];         // [k][chunk][granule] fp16 W
__device__ float gP2[(size_t)NN * KK];     // part2 + bias

// ---------------- helpers ----------------
static __device__ __forceinline__ uint32_t s2u(const void* p) {
    uint32_t a;
    asm("{ .reg .u64 t; cvta.to.shared.u64 t, %1; cvt.u32.u64 %0, t; }"
        : "=r"(a) : "l"(p));
    return a;
}
static __device__ __forceinline__ uint32_t packh2(float a, float b) {
    __half2 h = __floats2half2_rn(a, b);
    return *reinterpret_cast<uint32_t*>(&h);
}

#define LDSM4T(R, addr)                                                         \
    asm volatile("ldmatrix.sync.aligned.m8n8.x4.trans.shared.b16 {%0,%1,%2,%3},[%4];" \
                 : "=r"((R)[0]), "=r"((R)[1]), "=r"((R)[2]), "=r"((R)[3])       \
                 : "r"(addr))

#define HMMA(C, A, B0, B1)                                                      \
    asm volatile("mma.sync.aligned.m16n8k16.row.col.f32.f16.f16.f32 "           \
                 "{%0,%1,%2,%3},{%4,%5,%6,%7},{%8,%9},{%0,%1,%2,%3};"           \
                 : "+f"((C)[0]), "+f"((C)[1]), "+f"((C)[2]), "+f"((C)[3])       \
                 : "r"((A).x), "r"((A).y), "r"((A).z), "r"((A).w),              \
                   "r"(B0), "r"(B1))

static __device__ __forceinline__ void cp16(uint32_t dst, const void* src) {
    asm volatile("cp.async.cg.shared.global [%0], [%1], 16;"
                 :: "r"(dst), "l"(src) : "memory");
}
static __device__ __forceinline__ void cp_commit() {
    asm volatile("cp.async.commit_group;" ::: "memory");
}
template <int N>
static __device__ __forceinline__ void cp_wait() {
    asm volatile("cp.async.wait_group %0;" :: "n"(N) : "memory");
}

// ---------------- prep: X -> fp16 A-fragments ----------------
__global__ __launch_bounds__(256) void prep_x(const float* __restrict__ x1,
                                              const float* __restrict__ x2) {
    int wid  = (blockIdx.x * 256 + threadIdx.x) >> 5;   // 0..4095
    int lane = threadIdx.x & 31;
    int m  = wid >> 11;
    int rt = wid & 2047;
    const float* x = m ? x2 : x1;
    const float* p0 = x + (size_t)(rt * 16 + (lane >> 2)) * DD;
    const float* p1 = p0 + 8 * DD;
    const int c0 = (lane & 3) * 2;
    #pragma unroll
    for (int ds = 0; ds < 8; ds++) {
        int c = ds * 16 + c0;
        float2 v0 = *(const float2*)(p0 + c);
        float2 v1 = *(const float2*)(p1 + c);
        float2 v2 = *(const float2*)(p0 + c + 8);
        float2 v3 = *(const float2*)(p1 + c + 8);
        gXfrag[m][rt][ds][lane] = make_uint4(packh2(v0.x, v0.y), packh2(v1.x, v1.y),
                                             packh2(v2.x, v2.y), packh2(v3.x, v3.y));
    }
}

// ---------------- prep: W -> fp16 granules ----------------
// t bits: e8:0-2, d:3-9, mat:10, ch:11, k:12-16
__global__ __launch_bounds__(256) void prep_w(const float* __restrict__ W1,
                                              const float* __restrict__ W2) {
    int t   = blockIdx.x * 256 + threadIdx.x;   // 0..131071
    int e8  = t & 7;
    int d   = (t >> 3) & 127;
    int mat = (t >> 10) & 1;
    int ch  = (t >> 11) & 1;
    int k   = t >> 12;
    const float* w = (mat ? W2 : W1) + (size_t)k * DD * DD + (size_t)d * DD
                   + ch * 64 + e8 * 8;
    uint32_t hh[4];
    #pragma unroll
    for (int j = 0; j < 4; j++) hh[j] = packh2(w[2 * j], w[2 * j + 1]);
    gWh[k][ch][mat * 1024 + d * 8 + e8] = make_uint4(hh[0], hh[1], hh[2], hh[3]);
}

// ---------------- prep: part2 + bias (exact fp32) ----------------
__global__ __launch_bounds__(256) void prep_p2(const float* __restrict__ x1,
                                               const float* __restrict__ x2,
                                               const float* __restrict__ Vg,
                                               const float* __restrict__ bg) {
    __shared__ float Vs[KK * 256];
    __shared__ float bs[KK];
    int tid = threadIdx.x;
    for (int i = tid; i < KK * 256; i += 256) Vs[i] = Vg[i];
    if (tid < KK) bs[tid] = bg[tid];
    __syncthreads();
    int n = blockIdx.x * 256 + tid;
    float acc[KK];
    #pragma unroll
    for (int k = 0; k < KK; k++) acc[k] = bs[k];
    const float4* xa = (const float4*)(x1 + (size_t)n * DD);
    const float4* xb = (const float4*)(x2 + (size_t)n * DD);
    #pragma unroll 4
    for (int f = 0; f < 32; f++) {
        float4 xv = xa[f];
        #pragma unroll
        for (int k = 0; k < KK; k++) {
            float4 vv = *(const float4*)(&Vs[k * 256 + f * 4]);
            acc[k] = fmaf(xv.x, vv.x, fmaf(xv.y, vv.y,
                     fmaf(xv.z, vv.z, fmaf(xv.w, vv.w, acc[k]))));
        }
    }
    #pragma unroll 4
    for (int f = 0; f < 32; f++) {
        float4 xv = xb[f];
        #pragma unroll
        for (int k = 0; k < KK; k++) {
            float4 vv = *(const float4*)(&Vs[k * 256 + 128 + f * 4]);
            acc[k] = fmaf(xv.x, vv.x, fmaf(xv.y, vv.y,
                     fmaf(xv.z, vv.z, fmaf(xv.w, vv.w, acc[k]))));
        }
    }
    #pragma unroll
    for (int k = 0; k < KK; k++) gP2[(size_t)n * KK + k] = acc[k];
}

// ---------------- main kernel ----------------
#define WROWB 144                    // 128B data (64 fp16 cols) + 16B pad
#define WPL   (128 * WROWB)          // 18432 per mat tile
#define CHUNKB (2 * WPL)             // 36864 per chunk (2 mats)
#define OFF_STG (2 * CHUNKB)         // 73728 (both chunks resident)
#define SMEM_MAIN (OFF_STG + 8 * 4096)  // 106496

__global__ __launch_bounds__(256, 2)
void ntn_main(float* __restrict__ out) {
    extern __shared__ char smem[];
    const uint32_t sb = s2u(smem);
    const int tid  = threadIdx.x;
    const int lane = tid & 31;
    const int w    = tid >> 5;     // warp 0..7: rows 32*w .. +31 (of 256)
    const int k     = blockIdx.y;
    const int rbase = blockIdx.x * 256;
    const int rtb   = blockIdx.x * 16 + w * 2;

    // ---- cp.async BOTH chunks upfront (disjoint buffers) ----
    #pragma unroll
    for (int ch = 0; ch < 2; ch++) {
        #pragma unroll
        for (int i = 0; i < 8; i++) {
            int idx = tid + 256 * i;            // 0..2047
            int mp  = idx >> 10;
            int d   = (idx >> 3) & 127;
            int e8  = idx & 7;
            cp16(sb + ch * CHUNKB + mp * WPL + d * WROWB + e8 * 16,
                 &gWh[k][ch][idx]);
        }
        cp_commit();
    }

    const int arow  = (lane & 7) + ((lane >> 3) & 1) * 8;
    const int half8 = lane >> 4;
    const uint32_t boff = (uint32_t)(arow * WROWB + half8 * 16);
    char* stg = smem + OFF_STG + w * 4096 + lane * 8;

    // ---- A register double-buffer: prefetch step (g=0, ds=0) ----
    uint4 a[2][2];
    a[0][0] = gXfrag[0][rtb][0][lane];
    a[0][1] = gXfrag[0][rtb + 1][0][lane];

    float dv[4]  = {0.f, 0.f, 0.f, 0.f};
    float n1v[4] = {0.f, 0.f, 0.f, 0.f};
    float n2v[4] = {0.f, 0.f, 0.f, 0.f};

    cp_wait<1>();
    __syncthreads();

    #pragma unroll 1
    for (int c = 0; c < 2; c++) {
        if (c == 1) { cp_wait<0>(); __syncthreads(); }
        const uint32_t cbuf = sb + c * CHUNKB;

        #pragma unroll 1
        for (int g = 0; g < 2; g++) {
            float cc[2][8][4];
            #pragma unroll
            for (int mt = 0; mt < 2; mt++)
                #pragma unroll
                for (int nt = 0; nt < 8; nt++)
                    #pragma unroll
                    for (int q = 0; q < 4; q++) cc[mt][nt][q] = 0.f;

            #pragma unroll
            for (int ds = 0; ds < 8; ds++) {
                const int cur = ds & 1, nxt = cur ^ 1;
                // prefetch next step's A: (g, ds+1) or (g^1, 0) at pass end
                const int gn = (ds < 7) ? g : (g ^ 1);
                const int dn = (ds < 7) ? (ds + 1) : 0;
                a[nxt][0] = gXfrag[gn][rtb][dn][lane];
                a[nxt][1] = gXfrag[gn][rtb + 1][dn][lane];

                uint32_t bb[4][4];
                const uint32_t tb = cbuf + g * WPL + (uint32_t)(ds * 16 * WROWB) + boff;
                LDSM4T(bb[0], tb);
                LDSM4T(bb[1], tb + 32);
                LDSM4T(bb[2], tb + 64);
                LDSM4T(bb[3], tb + 96);

                #pragma unroll
                for (int cb = 0; cb < 4; cb++) {
                    HMMA(cc[0][cb * 2],     a[cur][0], bb[cb][0], bb[cb][1]);
                    HMMA(cc[1][cb * 2],     a[cur][1], bb[cb][0], bb[cb][1]);
                    HMMA(cc[0][cb * 2 + 1], a[cur][0], bb[cb][2], bb[cb][3]);
                    HMMA(cc[1][cb * 2 + 1], a[cur][1], bb[cb][2], bb[cb][3]);
                }
            }

            if (g == 0) {
                // stage x1t tile as fp16 pairs (warp-private; no sync needed)
                #pragma unroll
                for (int mt = 0; mt < 2; mt++)
                    #pragma unroll
                    for (int nt = 0; nt < 8; nt++) {
                        uint2 pv;
                        pv.x = packh2(cc[mt][nt][0], cc[mt][nt][1]);
                        pv.y = packh2(cc[mt][nt][2], cc[mt][nt][3]);
                        *(uint2*)(stg + (mt * 8 + nt) * 256) = pv;
                    }
            } else {
                // fold: x1t (staged fp16) against x2t (cc)
                #pragma unroll
                for (int mt = 0; mt < 2; mt++)
                    #pragma unroll
                    for (int nt = 0; nt < 8; nt++) {
                        uint2 pv = *(const uint2*)(stg + (mt * 8 + nt) * 256);
                        float2 f0 = __half22float2(*reinterpret_cast<__half2*>(&pv.x));
                        float2 f1 = __half22float2(*reinterpret_cast<__half2*>(&pv.y));
                        const int s0 = mt * 2;
                        float b0 = cc[mt][nt][0], b1 = cc[mt][nt][1];
                        float b2 = cc[mt][nt][2], b3 = cc[mt][nt][3];
                        dv[s0]      = fmaf(f0.x, b0, fmaf(f0.y, b1, dv[s0]));
                        n1v[s0]     = fmaf(f0.x, f0.x, fmaf(f0.y, f0.y, n1v[s0]));
                        n2v[s0]     = fmaf(b0, b0, fmaf(b1, b1, n2v[s0]));
                        dv[s0 + 1]  = fmaf(f1.x, b2, fmaf(f1.y, b3, dv[s0 + 1]));
                        n1v[s0 + 1] = fmaf(f1.x, f1.x, fmaf(f1.y, f1.y, n1v[s0 + 1]));
                        n2v[s0 + 1] = fmaf(b2, b2, fmaf(b3, b3, n2v[s0 + 1]));
                    }
            }
        }
    }

    // ---- lane reduce (4 lanes share a row); rows are warp-exclusive ----
    #pragma unroll
    for (int s = 0; s < 4; s++) {
        #pragma unroll
        for (int off = 1; off <= 2; off <<= 1) {
            dv[s]  += __shfl_xor_sync(0xffffffffu, dv[s],  off);
            n1v[s] += __shfl_xor_sync(0xffffffffu, n1v[s], off);
            n2v[s] += __shfl_xor_sync(0xffffffffu, n2v[s], off);
        }
    }
    if ((lane & 3) == 0) {
        #pragma unroll
        for (int s = 0; s < 4; s++) {
            const int row = w * 32 + (s >> 1) * 16 + (s & 1) * 8 + (lane >> 2);
            float s1 = fmaxf(sqrtf(n1v[s]), EPSN);
            float s2 = fmaxf(sqrtf(n2v[s]), EPSN);
            float v  = dv[s] / (s1 * s2) + gP2[(size_t)(rbase + row) * KK + k];
            out[(size_t)(rbase + row) * KK + k] = fmaxf(v, 0.f);
        }
    }
}

extern "C" void kernel_launch(void* const* d_in, const int* in_sizes, int n_in,
                              void* d_out, int out_size) {
    const float* x1 = (const float*)d_in[0];
    const float* x2 = (const float*)d_in[1];
    const float* W1 = (const float*)d_in[2];
    const float* W2 = (const float*)d_in[3];
    const float* V  = (const float*)d_in[4];
    const float* b  = (const float*)d_in[5];
    float* out = (float*)d_out;

    prep_x<<<512, 256>>>(x1, x2);
    prep_w<<<512, 256>>>(W1, W2);
    prep_p2<<<NN / 256, 256>>>(x1, x2, V, b);

    cudaFuncSetAttribute(ntn_main,
                         cudaFuncAttributeMaxDynamicSharedMemorySize, SMEM_MAIN);
    dim3 grid(NN / 256, KK);
    ntn_main<<<grid, 256, SMEM_MAIN>>>(out);
}